// round 6
// baseline (speedup 1.0000x reference)
#include <cuda_runtime.h>
#include <cuda_bf16.h>
#include <cstdint>

// ---------------- problem dims ----------------
#define MTOT 8192
#define DIN  1600
#define DOUT 4800
#define RANK 8
#define LORA_SCALE 4.0f

// ---------------- GEMM tiling ----------------
#define MT 128
#define NT 192
#define KCH 32                 // K elems per pipeline stage
#define NSTAGE 4
#define THREADS 256
#define CPS (DIN / KCH)        // 50 chunks per K-section
#define NCH (3 * CPS)          // 150 total chunks (3 emulation sections)

// smem: padded rows, stride 40 bf16 = 80B -> conflict-free ldmatrix
#define SA_STRIDE 40
#define A_STAGE_B (MT * SA_STRIDE * 2)          // 10240
#define B_STAGE_B (NT * SA_STRIDE * 2)          // 15360
#define STAGE_B   (A_STAGE_B + B_STAGE_B)       // 25600
#define GEMM_SMEM (NSTAGE * STAGE_B)            // 102400

// ---------------- device scratch (no runtime alloc allowed) ----------------
__device__ __nv_bfloat16 g_xh[(size_t)MTOT * DIN];
__device__ __nv_bfloat16 g_xl[(size_t)MTOT * DIN];
__device__ __nv_bfloat16 g_wth[(size_t)DOUT * DIN];   // W^T [n][k]
__device__ __nv_bfloat16 g_wtl[(size_t)DOUT * DIN];
__device__ float         g_xa[(size_t)MTOT * RANK];   // x @ lora_A

// ---------------- helpers ----------------
__device__ __forceinline__ uint32_t smem_u32(const void* p) {
    uint32_t a;
    asm("{ .reg .u64 t; cvta.to.shared.u64 t, %1; cvt.u32.u64 %0, t; }" : "=r"(a) : "l"(p));
    return a;
}

#define LDSM4(R0, R1, R2, R3, addr)                                           \
    asm volatile("ldmatrix.sync.aligned.m8n8.x4.shared.b16 {%0,%1,%2,%3}, [%4];" \
                 : "=r"(R0), "=r"(R1), "=r"(R2), "=r"(R3) : "r"(addr))

__device__ __forceinline__ void mma16816(float* d, const uint32_t* a, const uint32_t* b) {
    asm volatile(
        "mma.sync.aligned.m16n8k16.row.col.f32.bf16.bf16.f32 "
        "{%0,%1,%2,%3}, {%4,%5,%6,%7}, {%8,%9}, {%0,%1,%2,%3};"
        : "+f"(d[0]), "+f"(d[1]), "+f"(d[2]), "+f"(d[3])
        : "r"(a[0]), "r"(a[1]), "r"(a[2]), "r"(a[3]), "r"(b[0]), "r"(b[1]));
}

// ---------------- prologue 1: split x into bf16 hi/lo ----------------
__global__ void lora6158_split_x(const float* __restrict__ x) {
    int i = blockIdx.x * blockDim.x + threadIdx.x;   // 4 elems per thread
    float4 v = ((const float4*)x)[i];
    __nv_bfloat16 h0 = __float2bfloat16(v.x), h1 = __float2bfloat16(v.y);
    __nv_bfloat16 h2 = __float2bfloat16(v.z), h3 = __float2bfloat16(v.w);
    __nv_bfloat16 l0 = __float2bfloat16(v.x - __bfloat162float(h0));
    __nv_bfloat16 l1 = __float2bfloat16(v.y - __bfloat162float(h1));
    __nv_bfloat16 l2 = __float2bfloat16(v.z - __bfloat162float(h2));
    __nv_bfloat16 l3 = __float2bfloat16(v.w - __bfloat162float(h3));
    __nv_bfloat162* ph = (__nv_bfloat162*)g_xh;
    __nv_bfloat162* pl = (__nv_bfloat162*)g_xl;
    ph[2 * i]     = __halves2bfloat162(h0, h1);
    ph[2 * i + 1] = __halves2bfloat162(h2, h3);
    pl[2 * i]     = __halves2bfloat162(l0, l1);
    pl[2 * i + 1] = __halves2bfloat162(l2, l3);
}

// ---------------- prologue 2: transpose + split W ----------------
__global__ void lora6158_split_wt(const float* __restrict__ W) {
    __shared__ float t[32][33];
    int nb = blockIdx.x * 32, kb = blockIdx.y * 32;
    int c = threadIdx.x & 31, r0 = threadIdx.x >> 5;
#pragma unroll
    for (int i = 0; i < 4; i++) {
        int k = r0 + i * 8;
        t[k][c] = W[(size_t)(kb + k) * DOUT + nb + c];
    }
    __syncthreads();
#pragma unroll
    for (int i = 0; i < 4; i++) {
        int n = r0 + i * 8;
        float v = t[c][n];
        __nv_bfloat16 h = __float2bfloat16(v);
        __nv_bfloat16 l = __float2bfloat16(v - __bfloat162float(h));
        size_t o = (size_t)(nb + n) * DIN + kb + c;
        g_wth[o] = h;
        g_wtl[o] = l;
    }
}

// ---------------- prologue 3: xa = x @ lora_A ----------------
__global__ void lora6158_xa(const float* __restrict__ x, const float* __restrict__ A) {
    int row = blockIdx.x * 8 + (threadIdx.x >> 5);
    int lane = threadIdx.x & 31;
    const float* xr = x + (size_t)row * DIN;
    float a[8] = {0, 0, 0, 0, 0, 0, 0, 0};
    for (int k = lane; k < DIN; k += 32) {
        float xv = __ldg(xr + k);
        const float4* p = (const float4*)(A + k * 8);
        float4 u = p[0], w = p[1];
        a[0] += xv * u.x; a[1] += xv * u.y; a[2] += xv * u.z; a[3] += xv * u.w;
        a[4] += xv * w.x; a[5] += xv * w.y; a[6] += xv * w.z; a[7] += xv * w.w;
    }
#pragma unroll
    for (int off = 16; off; off >>= 1)
#pragma unroll
        for (int r = 0; r < 8; r++) a[r] += __shfl_xor_sync(0xffffffffu, a[r], off);
    if (lane == 0) {
        float4* o = (float4*)(g_xa + (size_t)row * 8);
        o[0] = make_float4(a[0], a[1], a[2], a[3]);
        o[1] = make_float4(a[4], a[5], a[6], a[7]);
    }
}

// ---------------- mainloop stage loader ----------------
__device__ __forceinline__ void load_stage(uint32_t sb, int stage,
                                           const __nv_bfloat16* __restrict__ Asrc,
                                           const __nv_bfloat16* __restrict__ Bsrc,
                                           int kk, int mBase, int nBase) {
    uint32_t stA = sb + stage * STAGE_B;
    uint32_t stB = stA + A_STAGE_B;
    // A: 128 rows x 64B = 512 x 16B chunks; B: 192 rows x 64B = 768 chunks
#pragma unroll
    for (int p = 0; p < 5; p++) {
        int i = threadIdx.x + p * THREADS;   // < 1280 always
        const char* src;
        uint32_t dst;
        if (i < 512) {
            int row = i >> 2, ch = i & 3;
            src = (const char*)(Asrc + (size_t)(mBase + row) * DIN + kk) + ch * 16;
            dst = stA + row * (SA_STRIDE * 2) + ch * 16;
        } else {
            int j = i - 512;
            int row = j >> 2, ch = j & 3;
            src = (const char*)(Bsrc + (size_t)(nBase + row) * DIN + kk) + ch * 16;
            dst = stB + row * (SA_STRIDE * 2) + ch * 16;
        }
        asm volatile("cp.async.cg.shared.global [%0], [%1], 16;" :: "r"(dst), "l"(src));
    }
}

// ---------------- main GEMM kernel (bf16 3-way emulated fp32) ----------------
__global__ void __launch_bounds__(THREADS, 1)
lora6158_gemm(const float* __restrict__ bias, const float* __restrict__ loraB,
              float* __restrict__ out) {
    extern __shared__ char smem[];
    uint32_t sb = smem_u32(smem);
    int tid = threadIdx.x, wid = tid >> 5, lane = tid & 31;
    int wm = wid >> 2, wn = wid & 3;              // 2 x 4 warp grid, 64x48 per warp
    int mBase = blockIdx.x * MT, nBase = blockIdx.y * NT;

    const __nv_bfloat16* Atab[3] = {g_xh, g_xl, g_xh};
    const __nv_bfloat16* Btab[3] = {g_wth, g_wth, g_wtl};

    // ldmatrix per-lane offsets (bytes, relative to stage A/B base)
    int jj = lane >> 3, rr = lane & 7;
    int lrow = (jj & 1) * 8 + rr;                 // row within 16-row ldsm tile
    int lcol = (jj >> 1) * 8;                     // col within 16-col k slab
    uint32_t aoff[4], boff[3];
#pragma unroll
    for (int mi = 0; mi < 4; mi++)
        aoff[mi] = ((wm * 64 + mi * 16 + lrow) * SA_STRIDE + lcol) * 2;
#pragma unroll
    for (int nb = 0; nb < 3; nb++)
        boff[nb] = A_STAGE_B + ((wn * 48 + nb * 16 + lrow) * SA_STRIDE + lcol) * 2;

    float acc[4][6][4];
#pragma unroll
    for (int mi = 0; mi < 4; mi++)
#pragma unroll
        for (int ni = 0; ni < 6; ni++)
#pragma unroll
            for (int q = 0; q < 4; q++) acc[mi][ni][q] = 0.f;

    // prefetch stages 0..2
#pragma unroll
    for (int c = 0; c < 3; c++) {
        load_stage(sb, c, Atab[0], Btab[0], c * KCH, mBase, nBase);
        asm volatile("cp.async.commit_group;");
    }

    for (int c = 0; c < NCH; c++) {
        int cn = c + 3;
        if (cn < NCH) {
            int sec = cn / CPS, kk = (cn % CPS) * KCH;
            load_stage(sb, cn & (NSTAGE - 1), Atab[sec], Btab[sec], kk, mBase, nBase);
        }
        asm volatile("cp.async.commit_group;");
        asm volatile("cp.async.wait_group 3;");
        __syncthreads();

        uint32_t stBase = sb + (c & (NSTAGE - 1)) * STAGE_B;
#pragma unroll
        for (int ks = 0; ks < 2; ks++) {
            uint32_t kb = ks * 32;                // 16 elems * 2B
            uint32_t a[4][4], b[6][2];
#pragma unroll
            for (int mi = 0; mi < 4; mi++)
                LDSM4(a[mi][0], a[mi][1], a[mi][2], a[mi][3], stBase + aoff[mi] + kb);
#pragma unroll
            for (int nb = 0; nb < 3; nb++) {
                uint32_t t0, t1, t2, t3;
                LDSM4(t0, t1, t2, t3, stBase + boff[nb] + kb);
                b[2 * nb][0] = t0; b[2 * nb + 1][0] = t1;
                b[2 * nb][1] = t2; b[2 * nb + 1][1] = t3;
            }
#pragma unroll
            for (int mi = 0; mi < 4; mi++)
#pragma unroll
                for (int ni = 0; ni < 6; ni++)
                    mma16816(acc[mi][ni], a[mi], b[ni]);
        }
        __syncthreads();
    }

    // ---------------- fused epilogue: bias + scaled LoRA ----------------
    float* s_lb   = (float*)smem;                 // [8][192] pre-scaled loraB tile
    float* s_bias = s_lb + RANK * NT;             // [192]
    float* s_xa   = s_bias + NT;                  // [128][8]
    for (int i = tid; i < RANK * NT; i += THREADS)
        s_lb[i] = loraB[(size_t)(i / NT) * DOUT + nBase + (i % NT)] * LORA_SCALE;
    for (int i = tid; i < NT; i += THREADS) s_bias[i] = bias[nBase + i];
    for (int i = tid; i < MT * RANK; i += THREADS) s_xa[i] = g_xa[(size_t)mBase * RANK + i];
    __syncthreads();

    int g = lane >> 2, tig = lane & 3;
#pragma unroll
    for (int mi = 0; mi < 4; mi++) {
#pragma unroll
        for (int h = 0; h < 2; h++) {
            int row_l = wm * 64 + mi * 16 + h * 8 + g;
            float xa[RANK];
#pragma unroll
            for (int r = 0; r < RANK; r++) xa[r] = s_xa[row_l * RANK + r];
            float* orow = out + (size_t)(mBase + row_l) * DOUT + nBase;
#pragma unroll
            for (int ni = 0; ni < 6; ni++) {
                int col = wn * 48 + ni * 8 + tig * 2;
                float v0 = acc[mi][ni][h * 2 + 0] + s_bias[col];
                float v1 = acc[mi][ni][h * 2 + 1] + s_bias[col + 1];
#pragma unroll
                for (int r = 0; r < RANK; r++) {
                    v0 += xa[r] * s_lb[r * NT + col];
                    v1 += xa[r] * s_lb[r * NT + col + 1];
                }
                *(float2*)(orow + col) = make_float2(v0, v1);
            }
        }
    }
}

// ---------------- launch ----------------
extern "C" void kernel_launch(void* const* d_in, const int* in_sizes, int n_in,
                              void* d_out, int out_size) {
    const float* x    = (const float*)d_in[0];
    const float* W    = (const float*)d_in[1];
    const float* bias = (const float*)d_in[2];
    const float* lA   = (const float*)d_in[3];
    const float* lB   = (const float*)d_in[4];
    float* out = (float*)d_out;

    cudaFuncSetAttribute(lora6158_gemm, cudaFuncAttributeMaxDynamicSharedMemorySize, GEMM_SMEM);

    lora6158_split_x<<<(MTOT * DIN) / 1024, 256>>>(x);
    dim3 wgrid(DOUT / 32, DIN / 32);
    lora6158_split_wt<<<wgrid, 256>>>(W);
    lora6158_xa<<<MTOT / 8, 256>>>(x, lA);

    dim3 ggrid(MTOT / MT, DOUT / NT);   // 64 x 25
    lora6158_gemm<<<ggrid, THREADS, GEMM_SMEM>>>(bias, lB, out);
}

// round 7
// speedup vs baseline: 1.0055x; 1.0055x over previous
#include <cuda_runtime.h>
#include <cuda_bf16.h>
#include <cstdint>

// ---------------- problem dims ----------------
#define MTOT 8192
#define DIN  1600
#define DOUT 4800
#define RANK 8
#define LORA_SCALE 4.0f

// ---------------- GEMM tiling ----------------
#define MT 128
#define NT 192
#define KCH 32                 // K elems per pipeline stage
#define NSTAGE 4
#define THREADS 384            // 12 warps: 2(M) x 6(N), warp tile 64x32
#define CPS (DIN / KCH)        // 50 chunks per K-section
#define NCH (3 * CPS)          // 150 total chunks (3 emulation sections)

// smem: padded rows, stride 40 bf16 = 80B -> conflict-free ldmatrix
#define SA_STRIDE 40
#define A_STAGE_B (MT * SA_STRIDE * 2)          // 10240
#define B_STAGE_B (NT * SA_STRIDE * 2)          // 15360
#define STAGE_B   (A_STAGE_B + B_STAGE_B)       // 25600
#define GEMM_SMEM (NSTAGE * STAGE_B)            // 102400

// ---------------- device scratch (no runtime alloc allowed) ----------------
__device__ __nv_bfloat16 g_xh[(size_t)MTOT * DIN];
__device__ __nv_bfloat16 g_xl[(size_t)MTOT * DIN];
__device__ __nv_bfloat16 g_wth[(size_t)DOUT * DIN];   // W^T [n][k]
__device__ __nv_bfloat16 g_wtl[(size_t)DOUT * DIN];
__device__ float         g_xa[(size_t)MTOT * RANK];   // x @ lora_A

// ---------------- helpers ----------------
__device__ __forceinline__ uint32_t smem_u32(const void* p) {
    uint32_t a;
    asm("{ .reg .u64 t; cvta.to.shared.u64 t, %1; cvt.u32.u64 %0, t; }" : "=r"(a) : "l"(p));
    return a;
}

#define LDSM4(R0, R1, R2, R3, addr)                                           \
    asm volatile("ldmatrix.sync.aligned.m8n8.x4.shared.b16 {%0,%1,%2,%3}, [%4];" \
                 : "=r"(R0), "=r"(R1), "=r"(R2), "=r"(R3) : "r"(addr))

__device__ __forceinline__ void mma16816(float* d, const uint32_t* a, const uint32_t* b) {
    asm volatile(
        "mma.sync.aligned.m16n8k16.row.col.f32.bf16.bf16.f32 "
        "{%0,%1,%2,%3}, {%4,%5,%6,%7}, {%8,%9}, {%0,%1,%2,%3};"
        : "+f"(d[0]), "+f"(d[1]), "+f"(d[2]), "+f"(d[3])
        : "r"(a[0]), "r"(a[1]), "r"(a[2]), "r"(a[3]), "r"(b[0]), "r"(b[1]));
}

// ---------------- prologue 1: split x into bf16 hi/lo ----------------
__global__ void lora6158_split_x(const float* __restrict__ x) {
    int i = blockIdx.x * blockDim.x + threadIdx.x;   // 4 elems per thread
    float4 v = ((const float4*)x)[i];
    __nv_bfloat16 h0 = __float2bfloat16(v.x), h1 = __float2bfloat16(v.y);
    __nv_bfloat16 h2 = __float2bfloat16(v.z), h3 = __float2bfloat16(v.w);
    __nv_bfloat16 l0 = __float2bfloat16(v.x - __bfloat162float(h0));
    __nv_bfloat16 l1 = __float2bfloat16(v.y - __bfloat162float(h1));
    __nv_bfloat16 l2 = __float2bfloat16(v.z - __bfloat162float(h2));
    __nv_bfloat16 l3 = __float2bfloat16(v.w - __bfloat162float(h3));
    __nv_bfloat162* ph = (__nv_bfloat162*)g_xh;
    __nv_bfloat162* pl = (__nv_bfloat162*)g_xl;
    ph[2 * i]     = __halves2bfloat162(h0, h1);
    ph[2 * i + 1] = __halves2bfloat162(h2, h3);
    pl[2 * i]     = __halves2bfloat162(l0, l1);
    pl[2 * i + 1] = __halves2bfloat162(l2, l3);
}

// ---------------- prologue 2: transpose + split W ----------------
__global__ void lora6158_split_wt(const float* __restrict__ W) {
    __shared__ float t[32][33];
    int nb = blockIdx.x * 32, kb = blockIdx.y * 32;
    int c = threadIdx.x & 31, r0 = threadIdx.x >> 5;
#pragma unroll
    for (int i = 0; i < 4; i++) {
        int k = r0 + i * 8;
        t[k][c] = W[(size_t)(kb + k) * DOUT + nb + c];
    }
    __syncthreads();
#pragma unroll
    for (int i = 0; i < 4; i++) {
        int n = r0 + i * 8;
        float v = t[c][n];
        __nv_bfloat16 h = __float2bfloat16(v);
        __nv_bfloat16 l = __float2bfloat16(v - __bfloat162float(h));
        size_t o = (size_t)(nb + n) * DIN + kb + c;
        g_wth[o] = h;
        g_wtl[o] = l;
    }
}

// ---------------- prologue 3: xa = x @ lora_A ----------------
__global__ void lora6158_xa(const float* __restrict__ x, const float* __restrict__ A) {
    int row = blockIdx.x * 8 + (threadIdx.x >> 5);
    int lane = threadIdx.x & 31;
    const float* xr = x + (size_t)row * DIN;
    float a[8] = {0, 0, 0, 0, 0, 0, 0, 0};
    for (int k = lane; k < DIN; k += 32) {
        float xv = __ldg(xr + k);
        const float4* p = (const float4*)(A + k * 8);
        float4 u = p[0], w = p[1];
        a[0] += xv * u.x; a[1] += xv * u.y; a[2] += xv * u.z; a[3] += xv * u.w;
        a[4] += xv * w.x; a[5] += xv * w.y; a[6] += xv * w.z; a[7] += xv * w.w;
    }
#pragma unroll
    for (int off = 16; off; off >>= 1)
#pragma unroll
        for (int r = 0; r < 8; r++) a[r] += __shfl_xor_sync(0xffffffffu, a[r], off);
    if (lane == 0) {
        float4* o = (float4*)(g_xa + (size_t)row * 8);
        o[0] = make_float4(a[0], a[1], a[2], a[3]);
        o[1] = make_float4(a[4], a[5], a[6], a[7]);
    }
}

// ---------------- mainloop stage loader ----------------
__device__ __forceinline__ void load_stage(uint32_t sb, int stage,
                                           const __nv_bfloat16* __restrict__ Asrc,
                                           const __nv_bfloat16* __restrict__ Bsrc,
                                           int kk, int mBase, int nBase) {
    uint32_t stA = sb + stage * STAGE_B;
    uint32_t stB = stA + A_STAGE_B;
    // A: 128 rows x 64B = 512 x 16B chunks; B: 192 rows x 64B = 768 chunks
    for (int i = threadIdx.x; i < 1280; i += THREADS) {
        const char* src;
        uint32_t dst;
        if (i < 512) {
            int row = i >> 2, ch = i & 3;
            src = (const char*)(Asrc + (size_t)(mBase + row) * DIN + kk) + ch * 16;
            dst = stA + row * (SA_STRIDE * 2) + ch * 16;
        } else {
            int j = i - 512;
            int row = j >> 2, ch = j & 3;
            src = (const char*)(Bsrc + (size_t)(nBase + row) * DIN + kk) + ch * 16;
            dst = stB + row * (SA_STRIDE * 2) + ch * 16;
        }
        asm volatile("cp.async.cg.shared.global [%0], [%1], 16;" :: "r"(dst), "l"(src));
    }
}

// ---------------- main GEMM kernel (bf16 3-way emulated fp32) ----------------
__global__ void __launch_bounds__(THREADS, 1)
lora6158_gemm(const float* __restrict__ bias, const float* __restrict__ loraB,
              float* __restrict__ out) {
    extern __shared__ char smem[];
    uint32_t sb = smem_u32(smem);
    int tid = threadIdx.x, wid = tid >> 5, lane = tid & 31;
    int wm = wid / 6, wn = wid % 6;               // 2 x 6 warp grid, 64x32 per warp
    int mBase = blockIdx.x * MT, nBase = blockIdx.y * NT;

    const __nv_bfloat16* Atab[3] = {g_xh, g_xl, g_xh};
    const __nv_bfloat16* Btab[3] = {g_wth, g_wth, g_wtl};

    // ldmatrix per-lane offsets (bytes, relative to stage base)
    int jj = lane >> 3, rr = lane & 7;
    int lrow = (jj & 1) * 8 + rr;                 // row within 16-row ldsm tile
    int lcol = (jj >> 1) * 8;                     // col within 16-col k slab
    uint32_t aoff[4], boff[2];
#pragma unroll
    for (int mi = 0; mi < 4; mi++)
        aoff[mi] = ((wm * 64 + mi * 16 + lrow) * SA_STRIDE + lcol) * 2;
#pragma unroll
    for (int nb = 0; nb < 2; nb++)
        boff[nb] = A_STAGE_B + ((wn * 32 + nb * 16 + lrow) * SA_STRIDE + lcol) * 2;

    float acc[4][4][4];
#pragma unroll
    for (int mi = 0; mi < 4; mi++)
#pragma unroll
        for (int ni = 0; ni < 4; ni++)
#pragma unroll
            for (int q = 0; q < 4; q++) acc[mi][ni][q] = 0.f;

    // prefetch stages 0..2
#pragma unroll
    for (int c = 0; c < NSTAGE - 1; c++) {
        load_stage(sb, c, Atab[0], Btab[0], c * KCH, mBase, nBase);
        asm volatile("cp.async.commit_group;");
    }

    for (int c = 0; c < NCH; c++) {
        asm volatile("cp.async.wait_group %0;" :: "n"(NSTAGE - 2));
        __syncthreads();

        // issue next load AFTER the barrier: stage (c+3)&3 was consumed in
        // iteration c-1, which every warp finished before this barrier.
        int cn = c + NSTAGE - 1;
        if (cn < NCH) {
            int sec = cn / CPS, kk = (cn % CPS) * KCH;
            load_stage(sb, cn & (NSTAGE - 1), Atab[sec], Btab[sec], kk, mBase, nBase);
        }
        asm volatile("cp.async.commit_group;");

        uint32_t stBase = sb + (c & (NSTAGE - 1)) * STAGE_B;
        // batch all fragment loads for both ks-steps, then all MMAs:
        // LDSM latency of ks1 hides under ks0's MMAs.
        uint32_t a[2][4][4], b[2][4][2];
#pragma unroll
        for (int ks = 0; ks < 2; ks++) {
            uint32_t kb = ks * 32;                // 16 elems * 2B
#pragma unroll
            for (int mi = 0; mi < 4; mi++)
                LDSM4(a[ks][mi][0], a[ks][mi][1], a[ks][mi][2], a[ks][mi][3],
                      stBase + aoff[mi] + kb);
#pragma unroll
            for (int nb = 0; nb < 2; nb++) {
                uint32_t t0, t1, t2, t3;
                LDSM4(t0, t1, t2, t3, stBase + boff[nb] + kb);
                b[ks][2 * nb][0] = t0; b[ks][2 * nb + 1][0] = t1;
                b[ks][2 * nb][1] = t2; b[ks][2 * nb + 1][1] = t3;
            }
        }
#pragma unroll
        for (int ks = 0; ks < 2; ks++)
#pragma unroll
            for (int mi = 0; mi < 4; mi++)
#pragma unroll
                for (int ni = 0; ni < 4; ni++)
                    mma16816(acc[mi][ni], a[ks][mi], b[ks][ni]);
    }
    __syncthreads();

    // ---------------- fused epilogue: bias + scaled LoRA ----------------
    float* s_lb   = (float*)smem;                 // [8][192] pre-scaled loraB tile
    float* s_bias = s_lb + RANK * NT;             // [192]
    float* s_xa   = s_bias + NT;                  // [128][8]
    for (int i = tid; i < RANK * NT; i += THREADS)
        s_lb[i] = loraB[(size_t)(i / NT) * DOUT + nBase + (i % NT)] * LORA_SCALE;
    for (int i = tid; i < NT; i += THREADS) s_bias[i] = bias[nBase + i];
    for (int i = tid; i < MT * RANK; i += THREADS) s_xa[i] = g_xa[(size_t)mBase * RANK + i];
    __syncthreads();

    int g = lane >> 2, tig = lane & 3;
#pragma unroll
    for (int mi = 0; mi < 4; mi++) {
#pragma unroll
        for (int h = 0; h < 2; h++) {
            int row_l = wm * 64 + mi * 16 + h * 8 + g;
            float xa[RANK];
#pragma unroll
            for (int r = 0; r < RANK; r++) xa[r] = s_xa[row_l * RANK + r];
            float* orow = out + (size_t)(mBase + row_l) * DOUT + nBase;
#pragma unroll
            for (int ni = 0; ni < 4; ni++) {
                int col = wn * 32 + ni * 8 + tig * 2;
                float v0 = acc[mi][ni][h * 2 + 0] + s_bias[col];
                float v1 = acc[mi][ni][h * 2 + 1] + s_bias[col + 1];
#pragma unroll
                for (int r = 0; r < RANK; r++) {
                    v0 += xa[r] * s_lb[r * NT + col];
                    v1 += xa[r] * s_lb[r * NT + col + 1];
                }
                *(float2*)(orow + col) = make_float2(v0, v1);
            }
        }
    }
}

// ---------------- launch ----------------
extern "C" void kernel_launch(void* const* d_in, const int* in_sizes, int n_in,
                              void* d_out, int out_size) {
    const float* x    = (const float*)d_in[0];
    const float* W    = (const float*)d_in[1];
    const float* bias = (const float*)d_in[2];
    const float* lA   = (const float*)d_in[3];
    const float* lB   = (const float*)d_in[4];
    float* out = (float*)d_out;

    cudaFuncSetAttribute(lora6158_gemm, cudaFuncAttributeMaxDynamicSharedMemorySize, GEMM_SMEM);

    lora6158_split_x<<<(MTOT * DIN) / 1024, 256>>>(x);
    dim3 wgrid(DOUT / 32, DIN / 32);
    lora6158_split_wt<<<wgrid, 256>>>(W);
    lora6158_xa<<<MTOT / 8, 256>>>(x, lA);

    dim3 ggrid(MTOT / MT, DOUT / NT);   // 64 x 25
    lora6158_gemm<<<ggrid, THREADS, GEMM_SMEM>>>(bias, lB, out);
}

// round 11
// speedup vs baseline: 1.0719x; 1.0660x over previous
#include <cuda_runtime.h>
#include <cuda_bf16.h>
#include <cstdint>

// ---------------- problem dims ----------------
#define MTOT 8192
#define DIN  1600
#define DOUT 4800
#define RANK 8
#define LORA_SCALE 4.0f

// ---------------- GEMM tiling ----------------
#define MT 128
#define NT 192
#define KCH 32                 // K elems per pipeline stage
#define NSTAGE 4
#define THREADS 384            // 12 warps: 2(M) x 6(N), warp tile 64x32
#define CPS (DIN / KCH)        // 50 chunks per K-section
#define NCH (3 * CPS)          // 150 total chunks (3 emulation sections)
#define NPAIR (NCH / 2)        // 75 pair-iterations

// smem: padded rows, stride 40 bf16 = 80B -> conflict-free ldmatrix
#define SA_STRIDE 40
#define A_STAGE_B (MT * SA_STRIDE * 2)          // 10240
#define B_STAGE_B (NT * SA_STRIDE * 2)          // 15360
#define STAGE_B   (A_STAGE_B + B_STAGE_B)       // 25600
#define GEMM_SMEM (NSTAGE * STAGE_B)            // 102400

// ---------------- device scratch (no runtime alloc allowed) ----------------
__device__ __nv_bfloat16 g_xh[(size_t)MTOT * DIN];
__device__ __nv_bfloat16 g_xl[(size_t)MTOT * DIN];
__device__ __nv_bfloat16 g_wth[(size_t)DOUT * DIN];   // W^T [n][k]
__device__ __nv_bfloat16 g_wtl[(size_t)DOUT * DIN];
__device__ float         g_xa[(size_t)MTOT * RANK];   // x @ lora_A

// ---------------- helpers ----------------
__device__ __forceinline__ uint32_t smem_u32(const void* p) {
    uint32_t a;
    asm("{ .reg .u64 t; cvta.to.shared.u64 t, %1; cvt.u32.u64 %0, t; }" : "=r"(a) : "l"(p));
    return a;
}

#define LDSM4(R0, R1, R2, R3, addr)                                           \
    asm volatile("ldmatrix.sync.aligned.m8n8.x4.shared.b16 {%0,%1,%2,%3}, [%4];" \
                 : "=r"(R0), "=r"(R1), "=r"(R2), "=r"(R3) : "r"(addr))

__device__ __forceinline__ void mma16816(float* d, const uint32_t* a, const uint32_t* b) {
    asm volatile(
        "mma.sync.aligned.m16n8k16.row.col.f32.bf16.bf16.f32 "
        "{%0,%1,%2,%3}, {%4,%5,%6,%7}, {%8,%9}, {%0,%1,%2,%3};"
        : "+f"(d[0]), "+f"(d[1]), "+f"(d[2]), "+f"(d[3])
        : "r"(a[0]), "r"(a[1]), "r"(a[2]), "r"(a[3]), "r"(b[0]), "r"(b[1]));
}

// ---------------- prologue 1: split x into bf16 hi/lo ----------------
__global__ void lora6158_split_x(const float* __restrict__ x) {
    int i = blockIdx.x * blockDim.x + threadIdx.x;   // 4 elems per thread
    float4 v = ((const float4*)x)[i];
    __nv_bfloat16 h0 = __float2bfloat16(v.x), h1 = __float2bfloat16(v.y);
    __nv_bfloat16 h2 = __float2bfloat16(v.z), h3 = __float2bfloat16(v.w);
    __nv_bfloat16 l0 = __float2bfloat16(v.x - __bfloat162float(h0));
    __nv_bfloat16 l1 = __float2bfloat16(v.y - __bfloat162float(h1));
    __nv_bfloat16 l2 = __float2bfloat16(v.z - __bfloat162float(h2));
    __nv_bfloat16 l3 = __float2bfloat16(v.w - __bfloat162float(h3));
    __nv_bfloat162* ph = (__nv_bfloat162*)g_xh;
    __nv_bfloat162* pl = (__nv_bfloat162*)g_xl;
    ph[2 * i]     = __halves2bfloat162(h0, h1);
    ph[2 * i + 1] = __halves2bfloat162(h2, h3);
    pl[2 * i]     = __halves2bfloat162(l0, l1);
    pl[2 * i + 1] = __halves2bfloat162(l2, l3);
}

// ---------------- prologue 2: transpose + split W ----------------
__global__ void lora6158_split_wt(const float* __restrict__ W) {
    __shared__ float t[32][33];
    int nb = blockIdx.x * 32, kb = blockIdx.y * 32;
    int c = threadIdx.x & 31, r0 = threadIdx.x >> 5;
#pragma unroll
    for (int i = 0; i < 4; i++) {
        int k = r0 + i * 8;
        t[k][c] = W[(size_t)(kb + k) * DOUT + nb + c];
    }
    __syncthreads();
#pragma unroll
    for (int i = 0; i < 4; i++) {
        int n = r0 + i * 8;
        float v = t[c][n];
        __nv_bfloat16 h = __float2bfloat16(v);
        __nv_bfloat16 l = __float2bfloat16(v - __bfloat162float(h));
        size_t o = (size_t)(nb + n) * DIN + kb + c;
        g_wth[o] = h;
        g_wtl[o] = l;
    }
}

// ---------------- prologue 3: xa = x @ lora_A ----------------
__global__ void lora6158_xa(const float* __restrict__ x, const float* __restrict__ A) {
    int row = blockIdx.x * 8 + (threadIdx.x >> 5);
    int lane = threadIdx.x & 31;
    const float* xr = x + (size_t)row * DIN;
    float a[8] = {0, 0, 0, 0, 0, 0, 0, 0};
    for (int k = lane; k < DIN; k += 32) {
        float xv = __ldg(xr + k);
        const float4* p = (const float4*)(A + k * 8);
        float4 u = p[0], w = p[1];
        a[0] += xv * u.x; a[1] += xv * u.y; a[2] += xv * u.z; a[3] += xv * u.w;
        a[4] += xv * w.x; a[5] += xv * w.y; a[6] += xv * w.z; a[7] += xv * w.w;
    }
#pragma unroll
    for (int off = 16; off; off >>= 1)
#pragma unroll
        for (int r = 0; r < 8; r++) a[r] += __shfl_xor_sync(0xffffffffu, a[r], off);
    if (lane == 0) {
        float4* o = (float4*)(g_xa + (size_t)row * 8);
        o[0] = make_float4(a[0], a[1], a[2], a[3]);
        o[1] = make_float4(a[4], a[5], a[6], a[7]);
    }
}

// ---------------- main GEMM kernel (bf16 3-way emulated fp32) ----------------
__global__ void __launch_bounds__(THREADS, 1)
lora6158_gemm(const float* __restrict__ bias, const float* __restrict__ loraB,
              float* __restrict__ out) {
    extern __shared__ char smem[];
    uint32_t sb = smem_u32(smem);
    int tid = threadIdx.x, wid = tid >> 5, lane = tid & 31;
    int wm = wid / 6, wn = wid % 6;               // 2 x 6 warp grid, 64x32 per warp
    int mBase = blockIdx.x * MT, nBase = blockIdx.y * NT;

    const __nv_bfloat16* Atab[3] = {g_xh, g_xl, g_xh};
    const __nv_bfloat16* Btab[3] = {g_wth, g_wth, g_wtl};

    // ---- precomputed cp.async slots (register-resident addressing) ----
    // 1280 16B transfers per chunk: slots s = tid + s*THREADS
    uint32_t s_dst[4];      // smem offset within stage
    uint32_t s_src[4];      // element offset within source matrix (incl. m/nBase)
    bool     s_isA[4], s_ok[4];
#pragma unroll
    for (int s = 0; s < 4; s++) {
        int i = tid + s * THREADS;
        s_ok[s] = (i < 1280);
        if (i < 512) {
            int row = i >> 2, ch = i & 3;
            s_isA[s] = true;
            s_dst[s] = row * (SA_STRIDE * 2) + ch * 16;
            s_src[s] = (uint32_t)((mBase + row) * DIN + ch * 8);
        } else {
            int j = (i - 512) & 1023;             // keep in-range even if !ok
            int row = j >> 2, ch = j & 3;
            s_isA[s] = false;
            s_dst[s] = A_STAGE_B + row * (SA_STRIDE * 2) + ch * 16;
            s_src[s] = (uint32_t)((nBase + row) * DIN + ch * 8);
        }
    }

    // ldmatrix per-lane offsets (bytes, relative to stage base)
    int jj = lane >> 3, rr = lane & 7;
    int lrow = (jj & 1) * 8 + rr;
    int lcol = (jj >> 1) * 8;
    uint32_t aoff[4], boff[2];
#pragma unroll
    for (int mi = 0; mi < 4; mi++)
        aoff[mi] = ((wm * 64 + mi * 16 + lrow) * SA_STRIDE + lcol) * 2;
#pragma unroll
    for (int nb = 0; nb < 2; nb++)
        boff[nb] = A_STAGE_B + ((wn * 32 + nb * 16 + lrow) * SA_STRIDE + lcol) * 2;

    float acc[4][4][4];
#pragma unroll
    for (int mi = 0; mi < 4; mi++)
#pragma unroll
        for (int ni = 0; ni < 4; ni++)
#pragma unroll
            for (int q = 0; q < 4; q++) acc[mi][ni][q] = 0.f;

    // loader: one chunk into `stage`, one commit_group
    auto load_chunk = [&](int stage, const __nv_bfloat16* Ab, const __nv_bfloat16* Bb,
                          int kk) {
        const __nv_bfloat16* a0 = Ab + kk;
        const __nv_bfloat16* b0 = Bb + kk;
        uint32_t stb = sb + stage * STAGE_B;
#pragma unroll
        for (int s = 0; s < 4; s++) {
            if (s_ok[s]) {
                const void* src = (const void*)((s_isA[s] ? a0 : b0) + s_src[s]);
                asm volatile("cp.async.cg.shared.global [%0], [%1], 16;"
                             :: "r"(stb + s_dst[s]), "l"(src));
            }
        }
        asm volatile("cp.async.commit_group;");
    };

    // compute: consume one chunk from `stage`
    auto compute_chunk = [&](int stage) {
        uint32_t stBase = sb + stage * STAGE_B;
        uint32_t a[2][4][4], b[2][4][2];
#pragma unroll
        for (int ks = 0; ks < 2; ks++) {
            uint32_t kb = ks * 32;
#pragma unroll
            for (int mi = 0; mi < 4; mi++)
                LDSM4(a[ks][mi][0], a[ks][mi][1], a[ks][mi][2], a[ks][mi][3],
                      stBase + aoff[mi] + kb);
#pragma unroll
            for (int nb = 0; nb < 2; nb++) {
                uint32_t t0, t1, t2, t3;
                LDSM4(t0, t1, t2, t3, stBase + boff[nb] + kb);
                b[ks][2 * nb][0] = t0; b[ks][2 * nb + 1][0] = t1;
                b[ks][2 * nb][1] = t2; b[ks][2 * nb + 1][1] = t3;
            }
        }
#pragma unroll
        for (int ks = 0; ks < 2; ks++)
#pragma unroll
            for (int mi = 0; mi < 4; mi++)
#pragma unroll
                for (int ni = 0; ni < 4; ni++)
                    mma16816(acc[mi][ni], a[ks][mi], b[ks][ni]);
    };

    // ---- prefetch chunks 0,1 ----
    load_chunk(0, Atab[0], Btab[0], 0);
    load_chunk(1, Atab[0], Btab[0], KCH);
    int lc = 2, lkk = 2 * KCH, lsec = 0;          // load-side counters

    // ---- paired mainloop: 1 wait + 1 sync per 2 chunks ----
    for (int it = 0; it < NPAIR; it++) {
        asm volatile("cp.async.wait_group 0;");
        __syncthreads();

        // issue next pair into the buffers consumed at iteration it-1
#pragma unroll
        for (int t = 0; t < 2; t++) {
            if (lc < NCH) {
                load_chunk(lc & (NSTAGE - 1), Atab[lsec], Btab[lsec], lkk);
                lc++;
                lkk += KCH;
                if (lkk == DIN) { lkk = 0; lsec++; }
            }
        }

        compute_chunk((2 * it) & (NSTAGE - 1));
        compute_chunk((2 * it + 1) & (NSTAGE - 1));
    }
    __syncthreads();

    // ---------------- fused epilogue: bias + scaled LoRA ----------------
    float* s_lb   = (float*)smem;                 // [8][192] pre-scaled loraB tile
    float* s_bias = s_lb + RANK * NT;             // [192]
    float* s_xa   = s_bias + NT;                  // [128][8]
    for (int i = tid; i < RANK * NT; i += THREADS)
        s_lb[i] = loraB[(size_t)(i / NT) * DOUT + nBase + (i % NT)] * LORA_SCALE;
    for (int i = tid; i < NT; i += THREADS) s_bias[i] = bias[nBase + i];
    for (int i = tid; i < MT * RANK; i += THREADS) s_xa[i] = g_xa[(size_t)mBase * RANK + i];
    __syncthreads();

    int g = lane >> 2, tig = lane & 3;
#pragma unroll
    for (int mi = 0; mi < 4; mi++) {
#pragma unroll
        for (int h = 0; h < 2; h++) {
            int row_l = wm * 64 + mi * 16 + h * 8 + g;
            float xa[RANK];
#pragma unroll
            for (int r = 0; r < RANK; r++) xa[r] = s_xa[row_l * RANK + r];
            float* orow = out + (size_t)(mBase + row_l) * DOUT + nBase;
#pragma unroll
            for (int ni = 0; ni < 4; ni++) {
                int col = wn * 32 + ni * 8 + tig * 2;
                float v0 = acc[mi][ni][h * 2 + 0] + s_bias[col];
                float v1 = acc[mi][ni][h * 2 + 1] + s_bias[col + 1];
#pragma unroll
                for (int r = 0; r < RANK; r++) {
                    v0 += xa[r] * s_lb[r * NT + col];
                    v1 += xa[r] * s_lb[r * NT + col + 1];
                }
                *(float2*)(orow + col) = make_float2(v0, v1);
            }
        }
    }
}

// ---------------- launch ----------------
extern "C" void kernel_launch(void* const* d_in, const int* in_sizes, int n_in,
                              void* d_out, int out_size) {
    const float* x    = (const float*)d_in[0];
    const float* W    = (const float*)d_in[1];
    const float* bias = (const float*)d_in[2];
    const float* lA   = (const float*)d_in[3];
    const float* lB   = (const float*)d_in[4];
    float* out = (float*)d_out;

    cudaFuncSetAttribute(lora6158_gemm, cudaFuncAttributeMaxDynamicSharedMemorySize, GEMM_SMEM);

    lora6158_split_x<<<(MTOT * DIN) / 1024, 256>>>(x);
    dim3 wgrid(DOUT / 32, DIN / 32);
    lora6158_split_wt<<<wgrid, 256>>>(W);
    lora6158_xa<<<MTOT / 8, 256>>>(x, lA);

    dim3 ggrid(MTOT / MT, DOUT / NT);   // 64 x 25
    lora6158_gemm<<<ggrid, THREADS, GEMM_SMEM>>>(bias, lB, out);
}

// round 17
// speedup vs baseline: 1.0993x; 1.0256x over previous
#include <cuda_runtime.h>
#include <cuda_bf16.h>
#include <cstdint>
#include <cstddef>

// ---------------- problem dims ----------------
#define MTOT 8192
#define DIN  1600
#define DOUT 4800
#define RANK 8
#define LORA_SCALE 4.0f

// ---------------- GEMM tiling ----------------
#define MT 128
#define NT 192
#define KCH 32                 // K elems per pipeline stage
#define NSTAGE 8
#define THREADS 384            // 12 warps: 2(M) x 6(N), warp tile 64x32
#define CPS (DIN / KCH)        // 50 chunks per K-section
#define NCH (3 * CPS)          // 150 total chunks (3 emulation sections)
#define NQUAD 37               // 37 quad iterations + 2-chunk tail

// smem: padded rows, stride 40 bf16 = 80B -> conflict-free ldmatrix
#define SA_STRIDE 40
#define A_STAGE_B (MT * SA_STRIDE * 2)          // 10240
#define B_STAGE_B (NT * SA_STRIDE * 2)          // 15360
#define STAGE_B   (A_STAGE_B + B_STAGE_B)       // 25600
#define GEMM_SMEM (NSTAGE * STAGE_B)            // 204800

// ---------------- device scratch (no runtime alloc allowed) ----------------
__device__ __nv_bfloat16 g_xh[(size_t)MTOT * DIN];
__device__ __nv_bfloat16 g_xl[(size_t)MTOT * DIN];
__device__ __nv_bfloat16 g_wth[(size_t)DOUT * DIN];   // W^T [n][k]
__device__ __nv_bfloat16 g_wtl[(size_t)DOUT * DIN];
__device__ float         g_xa[(size_t)MTOT * RANK];   // x @ lora_A

// ---------------- helpers ----------------
__device__ __forceinline__ uint32_t smem_u32(const void* p) {
    uint32_t a;
    asm("{ .reg .u64 t; cvta.to.shared.u64 t, %1; cvt.u32.u64 %0, t; }" : "=r"(a) : "l"(p));
    return a;
}

#define LDSM4(R0, R1, R2, R3, addr)                                           \
    asm volatile("ldmatrix.sync.aligned.m8n8.x4.shared.b16 {%0,%1,%2,%3}, [%4];" \
                 : "=r"(R0), "=r"(R1), "=r"(R2), "=r"(R3) : "r"(addr))

__device__ __forceinline__ void mma16816(float* d, const uint32_t* a, const uint32_t* b) {
    asm volatile(
        "mma.sync.aligned.m16n8k16.row.col.f32.bf16.bf16.f32 "
        "{%0,%1,%2,%3}, {%4,%5,%6,%7}, {%8,%9}, {%0,%1,%2,%3};"
        : "+f"(d[0]), "+f"(d[1]), "+f"(d[2]), "+f"(d[3])
        : "r"(a[0]), "r"(a[1]), "r"(a[2]), "r"(a[3]), "r"(b[0]), "r"(b[1]));
}

// ---------------- prologue 1: split x into bf16 hi/lo ----------------
__global__ void lora6158_split_x(const float* __restrict__ x) {
    int i = blockIdx.x * blockDim.x + threadIdx.x;   // 4 elems per thread
    float4 v = ((const float4*)x)[i];
    __nv_bfloat16 h0 = __float2bfloat16(v.x), h1 = __float2bfloat16(v.y);
    __nv_bfloat16 h2 = __float2bfloat16(v.z), h3 = __float2bfloat16(v.w);
    __nv_bfloat16 l0 = __float2bfloat16(v.x - __bfloat162float(h0));
    __nv_bfloat16 l1 = __float2bfloat16(v.y - __bfloat162float(h1));
    __nv_bfloat16 l2 = __float2bfloat16(v.z - __bfloat162float(h2));
    __nv_bfloat16 l3 = __float2bfloat16(v.w - __bfloat162float(h3));
    __nv_bfloat162* ph = (__nv_bfloat162*)g_xh;
    __nv_bfloat162* pl = (__nv_bfloat162*)g_xl;
    ph[2 * i]     = __halves2bfloat162(h0, h1);
    ph[2 * i + 1] = __halves2bfloat162(h2, h3);
    pl[2 * i]     = __halves2bfloat162(l0, l1);
    pl[2 * i + 1] = __halves2bfloat162(l2, l3);
}

// ---------------- prologue 2: transpose + split W ----------------
__global__ void lora6158_split_wt(const float* __restrict__ W) {
    __shared__ float t[32][33];
    int nb = blockIdx.x * 32, kb = blockIdx.y * 32;
    int c = threadIdx.x & 31, r0 = threadIdx.x >> 5;
#pragma unroll
    for (int i = 0; i < 4; i++) {
        int k = r0 + i * 8;
        t[k][c] = W[(size_t)(kb + k) * DOUT + nb + c];
    }
    __syncthreads();
#pragma unroll
    for (int i = 0; i < 4; i++) {
        int n = r0 + i * 8;
        float v = t[c][n];
        __nv_bfloat16 h = __float2bfloat16(v);
        __nv_bfloat16 l = __float2bfloat16(v - __bfloat162float(h));
        size_t o = (size_t)(nb + n) * DIN + kb + c;
        g_wth[o] = h;
        g_wtl[o] = l;
    }
}

// ---------------- prologue 3: xa = x @ lora_A ----------------
__global__ void lora6158_xa(const float* __restrict__ x, const float* __restrict__ A) {
    int row = blockIdx.x * 8 + (threadIdx.x >> 5);
    int lane = threadIdx.x & 31;
    const float* xr = x + (size_t)row * DIN;
    float a[8] = {0, 0, 0, 0, 0, 0, 0, 0};
    for (int k = lane; k < DIN; k += 32) {
        float xv = __ldg(xr + k);
        const float4* p = (const float4*)(A + k * 8);
        float4 u = p[0], w = p[1];
        a[0] += xv * u.x; a[1] += xv * u.y; a[2] += xv * u.z; a[3] += xv * u.w;
        a[4] += xv * w.x; a[5] += xv * w.y; a[6] += xv * w.z; a[7] += xv * w.w;
    }
#pragma unroll
    for (int off = 16; off; off >>= 1)
#pragma unroll
        for (int r = 0; r < 8; r++) a[r] += __shfl_xor_sync(0xffffffffu, a[r], off);
    if (lane == 0) {
        float4* o = (float4*)(g_xa + (size_t)row * 8);
        o[0] = make_float4(a[0], a[1], a[2], a[3]);
        o[1] = make_float4(a[4], a[5], a[6], a[7]);
    }
}

// ---------------- main GEMM kernel (bf16 3-way emulated fp32) ----------------
__global__ void __launch_bounds__(THREADS, 1)
lora6158_gemm(const float* __restrict__ bias, const float* __restrict__ loraB,
              float* __restrict__ out) {
    extern __shared__ char smem[];
    uint32_t sb = smem_u32(smem);
    int tid = threadIdx.x, wid = tid >> 5, lane = tid & 31;
    int wm = wid / 6, wn = wid % 6;               // 2 x 6 warp grid, 64x32 per warp
    int mBase = blockIdx.x * MT, nBase = blockIdx.y * NT;

    // ---- cp.async slots with live pointers (incremental addressing) ----
    // 1280 16B transfers per chunk: slots s = tid + s*THREADS
    uint32_t    s_dst[4];      // smem offset within stage
    const char* s_ptr[4];      // live gmem pointer, advanced 64B per chunk
    bool        s_isA[4], s_ok[4];
#pragma unroll
    for (int s = 0; s < 4; s++) {
        int i = tid + s * THREADS;
        s_ok[s] = (i < 1280);
        if (i < 512) {
            int row = i >> 2, ch = i & 3;
            s_isA[s] = true;
            s_dst[s] = row * (SA_STRIDE * 2) + ch * 16;
            s_ptr[s] = (const char*)(g_xh + (size_t)(mBase + row) * DIN + ch * 8);
        } else {
            int j = (i - 512) & 1023;             // keep in-range even if !ok
            int row = j >> 2, ch = j & 3;
            s_isA[s] = false;
            s_dst[s] = A_STAGE_B + row * (SA_STRIDE * 2) + ch * 16;
            s_ptr[s] = (const char*)(g_wth + (size_t)(nBase + row) * DIN + ch * 8);
        }
    }

    // ldmatrix per-lane offsets (bytes, relative to stage base)
    int jj = lane >> 3, rr = lane & 7;
    int lrow = (jj & 1) * 8 + rr;
    int lcol = (jj >> 1) * 8;
    uint32_t aoff[4], boff[2];
#pragma unroll
    for (int mi = 0; mi < 4; mi++)
        aoff[mi] = ((wm * 64 + mi * 16 + lrow) * SA_STRIDE + lcol) * 2;
#pragma unroll
    for (int nb = 0; nb < 2; nb++)
        boff[nb] = A_STAGE_B + ((wn * 32 + nb * 16 + lrow) * SA_STRIDE + lcol) * 2;

    float acc[4][4][4];
#pragma unroll
    for (int mi = 0; mi < 4; mi++)
#pragma unroll
        for (int ni = 0; ni < 4; ni++)
#pragma unroll
            for (int q = 0; q < 4; q++) acc[mi][ni][q] = 0.f;

    int csec = 0, secidx = 0;   // chunks loaded within current section / section idx

    // loader: one chunk into `stage`; advances all slot pointers by 64B and
    // applies the per-section base delta at section boundaries.
    auto load_chunk = [&](int stage) {
        uint32_t stb = sb + stage * STAGE_B;
#pragma unroll
        for (int s = 0; s < 4; s++) {
            if (s_ok[s]) {
                asm volatile("cp.async.cg.shared.global [%0], [%1], 16;"
                             :: "r"(stb + s_dst[s]), "l"(s_ptr[s]));
            }
            s_ptr[s] += KCH * 2;
        }
        asm volatile("cp.async.commit_group;");
        if (++csec == CPS) {
            csec = 0;
            if (secidx < 2) {
                // section 0->1: A xh->xl, B unchanged; section 1->2: A xl->xh, B wth->wtl
                ptrdiff_t dA = (secidx == 0)
                                   ? ((const char*)g_xl - (const char*)g_xh)
                                   : ((const char*)g_xh - (const char*)g_xl);
                ptrdiff_t dB = (secidx == 0)
                                   ? (ptrdiff_t)0
                                   : ((const char*)g_wtl - (const char*)g_wth);
                ptrdiff_t corr = -(ptrdiff_t)(DIN * 2);   // rewind K advance
#pragma unroll
                for (int s = 0; s < 4; s++)
                    s_ptr[s] += (s_isA[s] ? dA : dB) + corr;
                secidx++;
            }
        }
    };

    // compute: consume one chunk from `stage`
    auto compute_chunk = [&](int stage) {
        uint32_t stBase = sb + stage * STAGE_B;
        uint32_t a[2][4][4], b[2][4][2];
#pragma unroll
        for (int ks = 0; ks < 2; ks++) {
            uint32_t kb = ks * 32;
#pragma unroll
            for (int mi = 0; mi < 4; mi++)
                LDSM4(a[ks][mi][0], a[ks][mi][1], a[ks][mi][2], a[ks][mi][3],
                      stBase + aoff[mi] + kb);
#pragma unroll
            for (int nb = 0; nb < 2; nb++) {
                uint32_t t0, t1, t2, t3;
                LDSM4(t0, t1, t2, t3, stBase + boff[nb] + kb);
                b[ks][2 * nb][0] = t0; b[ks][2 * nb + 1][0] = t1;
                b[ks][2 * nb][1] = t2; b[ks][2 * nb + 1][1] = t3;
            }
        }
#pragma unroll
        for (int ks = 0; ks < 2; ks++)
#pragma unroll
            for (int mi = 0; mi < 4; mi++)
#pragma unroll
                for (int ni = 0; ni < 4; ni++)
                    mma16816(acc[mi][ni], a[ks][mi], b[ks][ni]);
    };

    // ---- prefetch chunks 0..3 into stages 0..3 ----
#pragma unroll
    for (int c = 0; c < 4; c++) load_chunk(c);
    int lc = 4;

    // ---- quad mainloop: 1 wait + 1 barrier per 4 chunks ----
    for (int it = 0; it < NQUAD; it++) {
        asm volatile("cp.async.wait_group 0;");
        __syncthreads();

        // issue next quad; stages being written were consumed at iteration it-1
#pragma unroll
        for (int t = 0; t < 4; t++) {
            if (lc < NCH) { load_chunk(lc & (NSTAGE - 1)); lc++; }
        }

        int cbase = 4 * it;
#pragma unroll
        for (int t = 0; t < 4; t++)
            compute_chunk((cbase + t) & (NSTAGE - 1));
    }
    // ---- tail: chunks 148, 149 ----
    asm volatile("cp.async.wait_group 0;");
    __syncthreads();
    compute_chunk(148 & (NSTAGE - 1));
    compute_chunk(149 & (NSTAGE - 1));
    __syncthreads();

    // ---------------- fused epilogue: bias + scaled LoRA ----------------
    float* s_lb   = (float*)smem;                 // [8][192] pre-scaled loraB tile
    float* s_bias = s_lb + RANK * NT;             // [192]
    float* s_xa   = s_bias + NT;                  // [128][8]
    for (int i = tid; i < RANK * NT; i += THREADS)
        s_lb[i] = loraB[(size_t)(i / NT) * DOUT + nBase + (i % NT)] * LORA_SCALE;
    for (int i = tid; i < NT; i += THREADS) s_bias[i] = bias[nBase + i];
    for (int i = tid; i < MT * RANK; i += THREADS) s_xa[i] = g_xa[(size_t)mBase * RANK + i];
    __syncthreads();

    int g = lane >> 2, tig = lane & 3;
#pragma unroll
    for (int mi = 0; mi < 4; mi++) {
#pragma unroll
        for (int h = 0; h < 2; h++) {
            int row_l = wm * 64 + mi * 16 + h * 8 + g;
            float xa[RANK];
#pragma unroll
            for (int r = 0; r < RANK; r++) xa[r] = s_xa[row_l * RANK + r];
            float* orow = out + (size_t)(mBase + row_l) * DOUT + nBase;
#pragma unroll
            for (int ni = 0; ni < 4; ni++) {
                int col = wn * 32 + ni * 8 + tig * 2;
                float v0 = acc[mi][ni][h * 2 + 0] + s_bias[col];
                float v1 = acc[mi][ni][h * 2 + 1] + s_bias[col + 1];
#pragma unroll
                for (int r = 0; r < RANK; r++) {
                    v0 += xa[r] * s_lb[r * NT + col];
                    v1 += xa[r] * s_lb[r * NT + col + 1];
                }
                *(float2*)(orow + col) = make_float2(v0, v1);
            }
        }
    }
}

// ---------------- launch ----------------
extern "C" void kernel_launch(void* const* d_in, const int* in_sizes, int n_in,
                              void* d_out, int out_size) {
    const float* x    = (const float*)d_in[0];
    const float* W    = (const float*)d_in[1];
    const float* bias = (const float*)d_in[2];
    const float* lA   = (const float*)d_in[3];
    const float* lB   = (const float*)d_in[4];
    float* out = (float*)d_out;

    cudaFuncSetAttribute(lora6158_gemm, cudaFuncAttributeMaxDynamicSharedMemorySize, GEMM_SMEM);

    lora6158_split_x<<<(MTOT * DIN) / 1024, 256>>>(x);
    dim3 wgrid(DOUT / 32, DIN / 32);
    lora6158_split_wt<<<wgrid, 256>>>(W);
    lora6158_xa<<<MTOT / 8, 256>>>(x, lA);

    dim3 ggrid(MTOT / MT, DOUT / NT);   // 64 x 25
    lora6158_gemm<<<ggrid, THREADS, GEMM_SMEM>>>(bias, lB, out);
}